// round 14
// baseline (speedup 1.0000x reference)
#include <cuda_runtime.h>
#include <cuda_fp16.h>
#include <cstdint>

#define BATCH 2
#define NSEQ 2048
#define DMODEL 1024
#define NHEAD 16
#define DHEAD 64
#define MTOT (BATCH*NSEQ)   // 4096

// ---------------- scratch (device globals; no allocation allowed) ----------------
__device__ __half g_xq[MTOT*DMODEL];
__device__ __half g_xk[MTOT*DMODEL];
__device__ __half g_xv[MTOT*DMODEL];
__device__ __half g_wq[DMODEL*DMODEL];
__device__ __half g_wk[DMODEL*DMODEL];
__device__ __half g_wv[DMODEL*DMODEL];
__device__ __half g_wo[DMODEL*DMODEL];
__device__ __half g_q [MTOT*DMODEL];   // [B,H,N,DH]
__device__ __half g_k [MTOT*DMODEL];   // [B,H,N,DH]
__device__ __half g_vt[MTOT*DMODEL];   // [B,H,DH,N]  (V transposed)
__device__ __half g_at[MTOT*DMODEL];   // attention out, [B,N,H,DH]

// ---------------- helpers ----------------
__device__ __forceinline__ void cp16(void* smem, const void* gmem) {
    uint32_t s = (uint32_t)__cvta_generic_to_shared(smem);
    asm volatile("cp.async.cg.shared.global [%0], [%1], 16;\n" :: "r"(s), "l"(gmem));
}
#define CP_COMMIT() asm volatile("cp.async.commit_group;\n" ::: "memory")
#define CP_WAIT0()  asm volatile("cp.async.wait_group 0;\n" ::: "memory")
#define CP_WAIT1()  asm volatile("cp.async.wait_group 1;\n" ::: "memory")

__device__ __forceinline__ uint32_t ld32(const __half* p) {
    return *reinterpret_cast<const uint32_t*>(p);
}
__device__ __forceinline__ uint32_t packh2(float a, float b) {
    __half2 h = __floats2half2_rn(a, b);
    return *reinterpret_cast<uint32_t*>(&h);
}
__device__ __forceinline__ uint32_t ex2h2(uint32_t x) {   // 2^x on a packed half2
    uint32_t r;
    asm("ex2.approx.f16x2 %0, %1;" : "=r"(r) : "r"(x));
    return r;
}
__device__ __forceinline__ void ldsm_x4(uint32_t& r0, uint32_t& r1,
                                        uint32_t& r2, uint32_t& r3,
                                        const __half* p) {
    uint32_t a = (uint32_t)__cvta_generic_to_shared(p);
    asm volatile("ldmatrix.sync.aligned.m8n8.x4.shared.b16 {%0,%1,%2,%3}, [%4];"
                 : "=r"(r0), "=r"(r1), "=r"(r2), "=r"(r3) : "r"(a));
}
// D = A(16x16, fp16) * B(16x8, fp16) + D, fp32 accum. row.col.
__device__ __forceinline__ void mma16816(float c[4],
                                         uint32_t a0, uint32_t a1, uint32_t a2, uint32_t a3,
                                         uint32_t b0, uint32_t b1) {
    asm volatile(
        "mma.sync.aligned.m16n8k16.row.col.f32.f16.f16.f32 "
        "{%0,%1,%2,%3}, {%4,%5,%6,%7}, {%8,%9}, {%0,%1,%2,%3};\n"
        : "+f"(c[0]), "+f"(c[1]), "+f"(c[2]), "+f"(c[3])
        : "r"(a0), "r"(a1), "r"(a2), "r"(a3), "r"(b0), "r"(b1));
}

// ---------------- fused fp32 -> fp16 convert (ONE launch) ----------------
__global__ void conv_all(const float* __restrict__ xq, const float* __restrict__ xk,
                         const float* __restrict__ xv,
                         const float* __restrict__ wq, const float* __restrict__ wk,
                         const float* __restrict__ wv, const float* __restrict__ wo) {
    int bid = blockIdx.x;
    const float* s;
    __half* d;
    int i;
    if (bid < 12288) {                       // activations: 3 x 4096 blocks
        int region = bid >> 12;
        i = (bid & 4095) * 256 + threadIdx.x;
        s = region == 0 ? xq : region == 1 ? xk : xv;
        d = region == 0 ? g_xq : region == 1 ? g_xk : g_xv;
    } else {                                 // weights: 4 x 1024 blocks
        bid -= 12288;
        int region = bid >> 10;
        i = (bid & 1023) * 256 + threadIdx.x;
        s = region == 0 ? wq : region == 1 ? wk : region == 2 ? wv : wo;
        d = region == 0 ? g_wq : region == 1 ? g_wk : region == 2 ? g_wv : g_wo;
    }
    float4 v = reinterpret_cast<const float4*>(s)[i];
    __half2* d2 = reinterpret_cast<__half2*>(d);
    d2[2*i]   = __floats2half2_rn(v.x, v.y);
    d2[2*i+1] = __floats2half2_rn(v.z, v.w);
}

// ---------------- GEMM core: 64x128 tile, 128 threads, 4 CTAs/SM ----------------
// C[4096,1024] = A[4096,1024] @ W[1024,1024]^T + bias
#define GBM 64
#define GBN 128
#define GBK 64
#define SAK2 72                        // padded smem stride (halves); 144B, 16B-aligned
#define ASTG (GBM*SAK2)                // 4608 halves per A stage
#define BSTG (GBN*SAK2)                // 9216 halves per B stage
#define GEMM_SMEM ((2*ASTG + 2*BSTG)*2)   // 55296 bytes

__device__ __forceinline__ void gemm_load(const __half* A, const __half* W,
                                          __half* sA, __half* sB,
                                          int bm, int bn, int k0, int tid) {
#pragma unroll
    for (int i = 0; i < 4; i++) {            // A: 64 rows x 8 16B-chunks
        int id = tid + i*128;
        int r = id >> 3, c = id & 7;
        cp16(&sA[r*SAK2 + c*8], A + (size_t)(bm + r)*DMODEL + k0 + c*8);
    }
#pragma unroll
    for (int i = 0; i < 8; i++) {            // B: 128 rows x 8 16B-chunks
        int id = tid + i*128;
        int r = id >> 3, c = id & 7;
        cp16(&sB[r*SAK2 + c*8], W + (size_t)(bn + r)*DMODEL + k0 + c*8);
    }
}

__device__ __forceinline__ void gemm_compute(const __half* sA, const __half* sB,
                                             float acc[2][8][4],
                                             int wm, int wn, int lr, int lc) {
#pragma unroll
    for (int ks = 0; ks < 4; ks++) {         // 4 x k16 per 64-chunk
        uint32_t af[2][4];
#pragma unroll
        for (int mi = 0; mi < 2; mi++) {
            const __half* p = &sA[(wm*32 + mi*16 + lr)*SAK2 + ks*16 + lc*8];
            ldsm_x4(af[mi][0], af[mi][1], af[mi][2], af[mi][3], p);
        }
        uint32_t bf[8][2];
#pragma unroll
        for (int np = 0; np < 4; np++) {
            uint32_t r0, r1, r2, r3;
            const __half* p = &sB[(wn*64 + np*16 + lr)*SAK2 + ks*16 + lc*8];
            ldsm_x4(r0, r1, r2, r3, p);
            bf[2*np][0]   = r0; bf[2*np][1]   = r2;
            bf[2*np+1][0] = r1; bf[2*np+1][1] = r3;
        }
#pragma unroll
        for (int mi = 0; mi < 2; mi++)
#pragma unroll
            for (int ni = 0; ni < 8; ni++)
                mma16816(acc[mi][ni], af[mi][0], af[mi][1], af[mi][2], af[mi][3],
                         bf[ni][0], bf[ni][1]);
    }
}

__device__ __forceinline__ void gemm_body(int mode, const __half* A, const __half* W,
                                          const float* bias, float* outf,
                                          int bm, int bn) {
    extern __shared__ __align__(16) __half gdyn[];
    __half* const sA0 = gdyn;
    __half* const sA1 = gdyn + ASTG;
    __half* const sB0 = gdyn + 2*ASTG;
    __half* const sB1 = gdyn + 2*ASTG + BSTG;

    const int tid  = threadIdx.x;
    const int lane = tid & 31, w = tid >> 5;     // 4 warps
    const int g = lane >> 2, l = lane & 3;
    const int wm = w & 1, wn = w >> 1;           // 2 warps along M, 2 along N
    const int lr = lane & 15, lc = lane >> 4;

    float acc[2][8][4];
#pragma unroll
    for (int mi = 0; mi < 2; mi++)
#pragma unroll
        for (int ni = 0; ni < 8; ni++)
#pragma unroll
            for (int r = 0; r < 4; r++) acc[mi][ni][r] = 0.f;

    gemm_load(A, W, sA0, sB0, bm, bn, 0, tid);
    CP_COMMIT();
    CP_WAIT0(); __syncthreads();

    const int KT = DMODEL / GBK;   // 16
    for (int kt = 0; kt < KT; kt += 2) {
        if (kt + 1 < KT) { gemm_load(A, W, sA1, sB1, bm, bn, (kt+1)*GBK, tid); CP_COMMIT(); }
        gemm_compute(sA0, sB0, acc, wm, wn, lr, lc);
        CP_WAIT0(); __syncthreads();
        if (kt + 2 < KT) { gemm_load(A, W, sA0, sB0, bm, bn, (kt+2)*GBK, tid); CP_COMMIT(); }
        if (kt + 1 < KT) gemm_compute(sA1, sB1, acc, wm, wn, lr, lc);
        CP_WAIT0(); __syncthreads();
    }

    // epilogue
#pragma unroll
    for (int mi = 0; mi < 2; mi++) {
#pragma unroll
        for (int ni = 0; ni < 8; ni++) {
            int c0 = bn + wn*64 + ni*8 + 2*l;
            float b0 = bias[c0], b1 = bias[c0 + 1];
#pragma unroll
            for (int rr = 0; rr < 2; rr++) {
                int r = bm + wm*32 + mi*16 + g + rr*8;
                float v0 = acc[mi][ni][rr*2]     + b0;
                float v1 = acc[mi][ni][rr*2 + 1] + b1;
                if (mode == 3) {
                    outf[(size_t)r*DMODEL + c0]     = v0;
                    outf[(size_t)r*DMODEL + c0 + 1] = v1;
                } else {
                    int bb = r >> 11, ns = r & 2047;
                    int hh = c0 >> 6, dh = c0 & 63;
                    if (mode == 2) {
                        size_t base = ((size_t)(bb*NHEAD + hh)*DHEAD + dh)*NSEQ + ns;
                        g_vt[base]        = __float2half_rn(v0);
                        g_vt[base + NSEQ] = __float2half_rn(v1);
                    } else {
                        __half* dst = (mode == 0 ? g_q : g_k);
                        size_t base = ((size_t)(bb*NHEAD + hh)*NSEQ + ns)*DHEAD + dh;
                        *reinterpret_cast<__half2*>(dst + base) =
                            __floats2half2_rn(v0, v1);
                    }
                }
            }
        }
    }
}

__global__ __launch_bounds__(128, 4) void gemm_qkv(const float* __restrict__ bq,
                                                   const float* __restrict__ bk,
                                                   const float* __restrict__ bv) {
    const int mode = blockIdx.z;
    const __half* A = mode == 0 ? g_xq : mode == 1 ? g_xk : g_xv;
    const __half* W = mode == 0 ? g_wq : mode == 1 ? g_wk : g_wv;
    const float* bias = mode == 0 ? bq : mode == 1 ? bk : bv;
    gemm_body(mode, A, W, bias, nullptr, blockIdx.y * GBM, blockIdx.x * GBN);
}

__global__ __launch_bounds__(128, 4) void gemm_o(const float* __restrict__ bo,
                                                 float* __restrict__ outf) {
    gemm_body(3, g_at, g_wo, bo, outf, blockIdx.y * GBM, blockIdx.x * GBN);
}

// ---------------- flash attention: 4-warp CTA (3 CTAs/SM), f16x2 exp, MMA rowsum ----------
// (unchanged — proven best config)
#define SKH (128*72)
#define SVH (64*136)
#define ATTN_SMEM ((2*SKH + 2*SVH) * 2)   // 71680 bytes
#define ONESH2 0x3C003C00u                // half2(1.0, 1.0)

__device__ __forceinline__ void attn_tile(const __half* __restrict__ cK,
                                          const __half* __restrict__ cV,
                                          const uint32_t qf[4][4],
                                          float oacc[8][4], float macc[4],
                                          int g, int l) {
    float sacc[16][4];
#pragma unroll
    for (int ni = 0; ni < 16; ni++) {
#pragma unroll
        for (int r = 0; r < 4; r++) sacc[ni][r] = 0.f;
        const __half* pb = &cK[(ni*8 + g)*72 + 2*l];
#pragma unroll
        for (int kk = 0; kk < 4; kk++)
            mma16816(sacc[ni], qf[kk][0], qf[kk][1], qf[kk][2], qf[kk][3],
                     ld32(pb + kk*16), ld32(pb + kk*16 + 8));
    }
    uint32_t pf[16][2];
#pragma unroll
    for (int ni = 0; ni < 16; ni++) {
        pf[ni][0] = ex2h2(packh2(sacc[ni][0], sacc[ni][1]));
        pf[ni][1] = ex2h2(packh2(sacc[ni][2], sacc[ni][3]));
    }
#pragma unroll
    for (int j = 0; j < 8; j++) {
        uint32_t ap0 = pf[2*j][0],   ap1 = pf[2*j][1];
        uint32_t ap2 = pf[2*j+1][0], ap3 = pf[2*j+1][1];
        mma16816(macc, ap0, ap1, ap2, ap3, ONESH2, ONESH2);
#pragma unroll
        for (int d = 0; d < 8; d++) {
            const __half* pb = &cV[(d*8 + g)*136 + j*16 + 2*l];
            mma16816(oacc[d], ap0, ap1, ap2, ap3, ld32(pb), ld32(pb + 8));
        }
    }
}

__global__ __launch_bounds__(128, 3) void attn_kernel() {
    extern __shared__ __align__(16) __half dyn[];
    __half* const sK0 = dyn;
    __half* const sK1 = dyn + SKH;
    __half* const sV0 = dyn + 2*SKH;
    __half* const sV1 = dyn + 2*SKH + SVH;

    const int tid  = threadIdx.x;
    const int lane = tid & 31, w = tid >> 5;
    const int g = lane >> 2, l = lane & 3;
    const int lr = lane & 15, lc = lane >> 4;
    const int qt = blockIdx.x, h = blockIdx.y, b = blockIdx.z;

    const size_t hb = (size_t)(b*NHEAD + h) * (NSEQ*DHEAD);
    const __half* Q  = g_q  + hb;
    const __half* K  = g_k  + hb;
    const __half* Vt = g_vt + hb;

    auto load_kv = [&](__half* dK, __half* dV, int kt) {
#pragma unroll
        for (int i = 0; i < 8; i++) {
            int id = tid + i*128;
            int r = id >> 3, c = id & 7;
            cp16(&dK[r*72 + c*8], K + (size_t)(kt*128 + r)*DHEAD + c*8);
        }
#pragma unroll
        for (int i = 0; i < 8; i++) {
            int id = tid + i*128;
            int r = id >> 4, c = id & 15;
            cp16(&dV[r*136 + c*8], Vt + (size_t)r*NSEQ + kt*128 + c*8);
        }
    };

#pragma unroll
    for (int i = 0; i < 4; i++) {
        int id = tid + i*128;
        int r = id >> 3, c = id & 7;
        cp16(&sK1[r*72 + c*8], Q + (size_t)(qt*64 + r)*DHEAD + c*8);
    }
    load_kv(sK0, sV0, 0);
    CP_COMMIT();
    CP_WAIT0(); __syncthreads();

    uint32_t qf[4][4];
#pragma unroll
    for (int kk = 0; kk < 4; kk++) {
        const __half* p = &sK1[(w*16 + lr)*72 + kk*16 + lc*8];
        ldsm_x4(qf[kk][0], qf[kk][1], qf[kk][2], qf[kk][3], p);
    }
    {
        const float qs = 0.125f * 1.4426950408889634f;   // 1/sqrt(DH) * log2(e)
        __half2 s2 = __floats2half2_rn(qs, qs);
#pragma unroll
        for (int kk = 0; kk < 4; kk++)
#pragma unroll
            for (int j = 0; j < 4; j++) {
                __half2 v = *reinterpret_cast<__half2*>(&qf[kk][j]);
                v = __hmul2(v, s2);
                qf[kk][j] = *reinterpret_cast<uint32_t*>(&v);
            }
    }
    __syncthreads();

    load_kv(sK1, sV1, 1);
    CP_COMMIT();

    float oacc[8][4];
#pragma unroll
    for (int d = 0; d < 8; d++)
#pragma unroll
        for (int r = 0; r < 4; r++) oacc[d][r] = 0.f;
    float macc[4] = {0.f, 0.f, 0.f, 0.f};

    const int KT = NSEQ/128;         // 16
    for (int kt = 0; kt < KT; kt += 2) {
        if (kt + 1 < KT) CP_WAIT1(); else CP_WAIT0();
        __syncthreads();
        attn_tile(sK0, sV0, qf, oacc, macc, g, l);
        __syncthreads();
        if (kt + 2 < KT) { load_kv(sK0, sV0, kt + 2); CP_COMMIT(); }
        if (kt + 2 < KT) CP_WAIT1(); else CP_WAIT0();
        __syncthreads();
        attn_tile(sK1, sV1, qf, oacc, macc, g, l);
        __syncthreads();
        if (kt + 3 < KT) { load_kv(sK1, sV1, kt + 3); CP_COMMIT(); }
    }

#pragma unroll
    for (int r = 0; r < 2; r++) {
        float inv = 1.f / macc[r*2];
        int qrow = qt*64 + w*16 + g + r*8;
        __half* dst = g_at + (size_t)(b*NSEQ + qrow)*DMODEL + h*DHEAD;
#pragma unroll
        for (int d = 0; d < 8; d++) {
            *reinterpret_cast<__half2*>(dst + d*8 + 2*l) =
                __floats2half2_rn(oacc[d][r*2]*inv, oacc[d][r*2+1]*inv);
        }
    }
}

// ---------------- launch ----------------
extern "C" void kernel_launch(void* const* d_in, const int* in_sizes, int n_in,
                              void* d_out, int out_size) {
    const float* xq = (const float*)d_in[0];
    const float* xk = (const float*)d_in[1];
    const float* xv = (const float*)d_in[2];
    const float* Wq = (const float*)d_in[3];
    const float* bq = (const float*)d_in[4];
    const float* Wk = (const float*)d_in[5];
    const float* bk = (const float*)d_in[6];
    const float* Wv = (const float*)d_in[7];
    const float* bv = (const float*)d_in[8];
    const float* Wo = (const float*)d_in[9];
    const float* bo = (const float*)d_in[10];
    float* out = (float*)d_out;

    cudaFuncSetAttribute(attn_kernel,
                         cudaFuncAttributeMaxDynamicSharedMemorySize, ATTN_SMEM);
    cudaFuncSetAttribute(gemm_qkv,
                         cudaFuncAttributeMaxDynamicSharedMemorySize, GEMM_SMEM);
    cudaFuncSetAttribute(gemm_o,
                         cudaFuncAttributeMaxDynamicSharedMemorySize, GEMM_SMEM);

    conv_all<<<16384, 256>>>(xq, xk, xv, Wq, Wk, Wv, Wo);          // launch 1

    dim3 qkvgrid(DMODEL/GBN, MTOT/GBM, 3);                          // (8, 64, 3)
    gemm_qkv<<<qkvgrid, 128, GEMM_SMEM>>>(bq, bk, bv);              // launch 2

    attn_kernel<<<dim3(NSEQ/64, NHEAD, BATCH), 128, ATTN_SMEM>>>(); // launch 3

    dim3 ogrid(DMODEL/GBN, MTOT/GBM);                               // (8, 64)
    gemm_o<<<ogrid, 128, GEMM_SMEM>>>(bo, out);                     // launch 4 -> ncu
}

// round 16
// speedup vs baseline: 1.0170x; 1.0170x over previous
#include <cuda_runtime.h>
#include <cuda_fp16.h>
#include <cstdint>

#define BATCH 2
#define NSEQ 2048
#define DMODEL 1024
#define NHEAD 16
#define DHEAD 64
#define MTOT (BATCH*NSEQ)   // 4096

// ---------------- scratch (device globals; no allocation allowed) ----------------
__device__ __half g_xq[MTOT*DMODEL];
__device__ __half g_xk[MTOT*DMODEL];
__device__ __half g_xv[MTOT*DMODEL];
__device__ __half g_wq[DMODEL*DMODEL];
__device__ __half g_wk[DMODEL*DMODEL];
__device__ __half g_wv[DMODEL*DMODEL];
__device__ __half g_wo[DMODEL*DMODEL];
__device__ __half g_q [MTOT*DMODEL];   // [B,H,N,DH]
__device__ __half g_k [MTOT*DMODEL];   // [B,H,N,DH]
__device__ __half g_vt[MTOT*DMODEL];   // [B,H,DH,N]  (V transposed)
__device__ __half g_at[MTOT*DMODEL];   // attention out, [B,N,H,DH]

// ---------------- helpers ----------------
__device__ __forceinline__ void cp16(void* smem, const void* gmem) {
    uint32_t s = (uint32_t)__cvta_generic_to_shared(smem);
    asm volatile("cp.async.cg.shared.global [%0], [%1], 16;\n" :: "r"(s), "l"(gmem));
}
#define CP_COMMIT() asm volatile("cp.async.commit_group;\n" ::: "memory")
#define CP_WAIT0()  asm volatile("cp.async.wait_group 0;\n" ::: "memory")
#define CP_WAIT1()  asm volatile("cp.async.wait_group 1;\n" ::: "memory")

__device__ __forceinline__ uint32_t ld32(const __half* p) {
    return *reinterpret_cast<const uint32_t*>(p);
}
__device__ __forceinline__ uint32_t packh2(float a, float b) {
    __half2 h = __floats2half2_rn(a, b);
    return *reinterpret_cast<uint32_t*>(&h);
}
__device__ __forceinline__ uint32_t ex2h2(uint32_t x) {   // 2^x on a packed half2
    uint32_t r;
    asm("ex2.approx.f16x2 %0, %1;" : "=r"(r) : "r"(x));
    return r;
}
__device__ __forceinline__ void ldsm_x4(uint32_t& r0, uint32_t& r1,
                                        uint32_t& r2, uint32_t& r3,
                                        const __half* p) {
    uint32_t a = (uint32_t)__cvta_generic_to_shared(p);
    asm volatile("ldmatrix.sync.aligned.m8n8.x4.shared.b16 {%0,%1,%2,%3}, [%4];"
                 : "=r"(r0), "=r"(r1), "=r"(r2), "=r"(r3) : "r"(a));
}
// D = A(16x16, fp16) * B(16x8, fp16) + D, fp32 accum. row.col.
__device__ __forceinline__ void mma16816(float c[4],
                                         uint32_t a0, uint32_t a1, uint32_t a2, uint32_t a3,
                                         uint32_t b0, uint32_t b1) {
    asm volatile(
        "mma.sync.aligned.m16n8k16.row.col.f32.f16.f16.f32 "
        "{%0,%1,%2,%3}, {%4,%5,%6,%7}, {%8,%9}, {%0,%1,%2,%3};\n"
        : "+f"(c[0]), "+f"(c[1]), "+f"(c[2]), "+f"(c[3])
        : "r"(a0), "r"(a1), "r"(a2), "r"(a3), "r"(b0), "r"(b1));
}

// ---------------- fused fp32 -> fp16 convert (ONE launch) ----------------
__global__ void conv_all(const float* __restrict__ xq, const float* __restrict__ xk,
                         const float* __restrict__ xv,
                         const float* __restrict__ wq, const float* __restrict__ wk,
                         const float* __restrict__ wv, const float* __restrict__ wo) {
    int bid = blockIdx.x;
    const float* s;
    __half* d;
    int i;
    if (bid < 12288) {                       // activations: 3 x 4096 blocks
        int region = bid >> 12;
        i = (bid & 4095) * 256 + threadIdx.x;
        s = region == 0 ? xq : region == 1 ? xk : xv;
        d = region == 0 ? g_xq : region == 1 ? g_xk : g_xv;
    } else {                                 // weights: 4 x 1024 blocks
        bid -= 12288;
        int region = bid >> 10;
        i = (bid & 1023) * 256 + threadIdx.x;
        s = region == 0 ? wq : region == 1 ? wk : region == 2 ? wv : wo;
        d = region == 0 ? g_wq : region == 1 ? g_wk : region == 2 ? g_wv : g_wo;
    }
    float4 v = reinterpret_cast<const float4*>(s)[i];
    __half2* d2 = reinterpret_cast<__half2*>(d);
    d2[2*i]   = __floats2half2_rn(v.x, v.y);
    d2[2*i+1] = __floats2half2_rn(v.z, v.w);
}

// ---------------- GEMM core: 128x128 tile, 256 threads, 3-stage pipeline ----------------
// C[4096,1024] = A[4096,1024] @ W[1024,1024]^T + bias
#define GBM 128
#define GBN 128
#define GBK 64
#define SAK2 72                        // padded smem stride (halves); 144B, 16B-aligned
#define MSTG (GBM*SAK2)                // 9216 halves per matrix per stage
#define GSTG2 (2*MSTG)                 // 18432 halves per stage (A+B)
#define GEMM_SMEM (3*GSTG2*2)          // 110592 bytes (3 stages)

__device__ __forceinline__ void gemm_load(const __half* A, const __half* W,
                                          __half* sA, __half* sB,
                                          int bm, int bn, int k0, int tid) {
#pragma unroll
    for (int i = 0; i < 4; i++) {            // A: 128 rows x 8 16B-chunks
        int id = tid + i*256;
        int r = id >> 3, c = id & 7;
        cp16(&sA[r*SAK2 + c*8], A + (size_t)(bm + r)*DMODEL + k0 + c*8);
    }
#pragma unroll
    for (int i = 0; i < 4; i++) {            // B: 128 rows x 8 16B-chunks
        int id = tid + i*256;
        int r = id >> 3, c = id & 7;
        cp16(&sB[r*SAK2 + c*8], W + (size_t)(bn + r)*DMODEL + k0 + c*8);
    }
}

__device__ __forceinline__ void gemm_compute(const __half* sA, const __half* sB,
                                             float acc[2][8][4],
                                             int wm, int wn, int lr, int lc) {
#pragma unroll
    for (int ks = 0; ks < 4; ks++) {         // 4 x k16 per 64-chunk
        uint32_t af[2][4];
#pragma unroll
        for (int mi = 0; mi < 2; mi++) {
            const __half* p = &sA[(wm*32 + mi*16 + lr)*SAK2 + ks*16 + lc*8];
            ldsm_x4(af[mi][0], af[mi][1], af[mi][2], af[mi][3], p);
        }
        uint32_t bf[8][2];
#pragma unroll
        for (int np = 0; np < 4; np++) {
            uint32_t r0, r1, r2, r3;
            const __half* p = &sB[(wn*64 + np*16 + lr)*SAK2 + ks*16 + lc*8];
            ldsm_x4(r0, r1, r2, r3, p);
            bf[2*np][0]   = r0; bf[2*np][1]   = r2;
            bf[2*np+1][0] = r1; bf[2*np+1][1] = r3;
        }
#pragma unroll
        for (int mi = 0; mi < 2; mi++)
#pragma unroll
            for (int ni = 0; ni < 8; ni++)
                mma16816(acc[mi][ni], af[mi][0], af[mi][1], af[mi][2], af[mi][3],
                         bf[ni][0], bf[ni][1]);
    }
}

__device__ __forceinline__ void gemm_body(int mode, const __half* A, const __half* W,
                                          const float* bias, float* outf,
                                          int bm, int bn) {
    extern __shared__ __align__(16) __half gdyn[];
    // three stages, compile-time offsets (no runtime pointer arrays)
    __half* const sA0 = gdyn;
    __half* const sB0 = gdyn + MSTG;
    __half* const sA1 = gdyn + GSTG2;
    __half* const sB1 = gdyn + GSTG2 + MSTG;
    __half* const sA2 = gdyn + 2*GSTG2;
    __half* const sB2 = gdyn + 2*GSTG2 + MSTG;

    const int tid  = threadIdx.x;
    const int lane = tid & 31, w = tid >> 5;
    const int g = lane >> 2, l = lane & 3;
    const int wm = w & 3, wn = w >> 2;          // 4 warps along M, 2 along N
    const int lr = lane & 15, lc = lane >> 4;

    float acc[2][8][4];
#pragma unroll
    for (int mi = 0; mi < 2; mi++)
#pragma unroll
        for (int ni = 0; ni < 8; ni++)
#pragma unroll
            for (int r = 0; r < 4; r++) acc[mi][ni][r] = 0.f;

    const int KT = DMODEL / GBK;   // 16

    // prologue: stages 0 and 1 in flight
    gemm_load(A, W, sA0, sB0, bm, bn, 0, tid);     CP_COMMIT();
    gemm_load(A, W, sA1, sB1, bm, bn, GBK, tid);   CP_COMMIT();
    CP_WAIT1(); __syncthreads();                   // tile 0 ready, tile 1 in flight

    // one sub-body: prefetch t+2 (distance 2), compute t, wait for t+1, sync
#define GEMM_STEP(T, SAp, SBp, SAc, SBc) do {                                   \
        if ((T) + 2 < KT) {                                                     \
            gemm_load(A, W, (SAp), (SBp), bm, bn, ((T)+2)*GBK, tid);            \
            CP_COMMIT();                                                        \
        }                                                                       \
        gemm_compute((SAc), (SBc), acc, wm, wn, lr, lc);                        \
        if ((T) + 2 < KT)      { CP_WAIT1(); }                                  \
        else if ((T) + 1 < KT) { CP_WAIT0(); }                                  \
        if ((T) + 1 < KT) __syncthreads();                                      \
    } while (0)

    // 15 tiles in 5 statically-unrolled triples, then the tail tile
    for (int kt = 0; kt < 15; kt += 3) {
        GEMM_STEP(kt,     sA2, sB2, sA0, sB0);   // compute buf0, prefetch into buf2
        GEMM_STEP(kt + 1, sA0, sB0, sA1, sB1);   // compute buf1, prefetch into buf0
        GEMM_STEP(kt + 2, sA1, sB1, sA2, sB2);   // compute buf2, prefetch into buf1
    }
    GEMM_STEP(15, sA2, sB2, sA0, sB0);           // tile 15 lives in buf0 (15%3==0)
#undef GEMM_STEP

    // epilogue
#pragma unroll
    for (int mi = 0; mi < 2; mi++) {
#pragma unroll
        for (int ni = 0; ni < 8; ni++) {
            int c0 = bn + wn*64 + ni*8 + 2*l;
            float b0 = bias[c0], b1 = bias[c0 + 1];
#pragma unroll
            for (int rr = 0; rr < 2; rr++) {
                int r = bm + wm*32 + mi*16 + g + rr*8;
                float v0 = acc[mi][ni][rr*2]     + b0;
                float v1 = acc[mi][ni][rr*2 + 1] + b1;
                if (mode == 3) {
                    outf[(size_t)r*DMODEL + c0]     = v0;
                    outf[(size_t)r*DMODEL + c0 + 1] = v1;
                } else {
                    int bb = r >> 11, ns = r & 2047;
                    int hh = c0 >> 6, dh = c0 & 63;
                    if (mode == 2) {
                        size_t base = ((size_t)(bb*NHEAD + hh)*DHEAD + dh)*NSEQ + ns;
                        g_vt[base]        = __float2half_rn(v0);
                        g_vt[base + NSEQ] = __float2half_rn(v1);
                    } else {
                        __half* dst = (mode == 0 ? g_q : g_k);
                        size_t base = ((size_t)(bb*NHEAD + hh)*NSEQ + ns)*DHEAD + dh;
                        *reinterpret_cast<__half2*>(dst + base) =
                            __floats2half2_rn(v0, v1);
                    }
                }
            }
        }
    }
}

__global__ __launch_bounds__(256) void gemm_qkv(const float* __restrict__ bq,
                                                const float* __restrict__ bk,
                                                const float* __restrict__ bv) {
    const int mode = blockIdx.z;
    const __half* A = mode == 0 ? g_xq : mode == 1 ? g_xk : g_xv;
    const __half* W = mode == 0 ? g_wq : mode == 1 ? g_wk : g_wv;
    const float* bias = mode == 0 ? bq : mode == 1 ? bk : bv;
    gemm_body(mode, A, W, bias, nullptr, blockIdx.y * GBM, blockIdx.x * GBN);
}

__global__ __launch_bounds__(256) void gemm_o(const float* __restrict__ bo,
                                              float* __restrict__ outf) {
    gemm_body(3, g_at, g_wo, bo, outf, blockIdx.y * GBM, blockIdx.x * GBN);
}

// ---------------- flash attention: 4-warp CTA (3 CTAs/SM), f16x2 exp, MMA rowsum ----------
// (unchanged — proven best config)
#define SKH (128*72)
#define SVH (64*136)
#define ATTN_SMEM ((2*SKH + 2*SVH) * 2)   // 71680 bytes
#define ONESH2 0x3C003C00u                // half2(1.0, 1.0)

__device__ __forceinline__ void attn_tile(const __half* __restrict__ cK,
                                          const __half* __restrict__ cV,
                                          const uint32_t qf[4][4],
                                          float oacc[8][4], float macc[4],
                                          int g, int l) {
    float sacc[16][4];
#pragma unroll
    for (int ni = 0; ni < 16; ni++) {
#pragma unroll
        for (int r = 0; r < 4; r++) sacc[ni][r] = 0.f;
        const __half* pb = &cK[(ni*8 + g)*72 + 2*l];
#pragma unroll
        for (int kk = 0; kk < 4; kk++)
            mma16816(sacc[ni], qf[kk][0], qf[kk][1], qf[kk][2], qf[kk][3],
                     ld32(pb + kk*16), ld32(pb + kk*16 + 8));
    }
    uint32_t pf[16][2];
#pragma unroll
    for (int ni = 0; ni < 16; ni++) {
        pf[ni][0] = ex2h2(packh2(sacc[ni][0], sacc[ni][1]));
        pf[ni][1] = ex2h2(packh2(sacc[ni][2], sacc[ni][3]));
    }
#pragma unroll
    for (int j = 0; j < 8; j++) {
        uint32_t ap0 = pf[2*j][0],   ap1 = pf[2*j][1];
        uint32_t ap2 = pf[2*j+1][0], ap3 = pf[2*j+1][1];
        mma16816(macc, ap0, ap1, ap2, ap3, ONESH2, ONESH2);
#pragma unroll
        for (int d = 0; d < 8; d++) {
            const __half* pb = &cV[(d*8 + g)*136 + j*16 + 2*l];
            mma16816(oacc[d], ap0, ap1, ap2, ap3, ld32(pb), ld32(pb + 8));
        }
    }
}

__global__ __launch_bounds__(128, 3) void attn_kernel() {
    extern __shared__ __align__(16) __half dyn[];
    __half* const sK0 = dyn;
    __half* const sK1 = dyn + SKH;
    __half* const sV0 = dyn + 2*SKH;
    __half* const sV1 = dyn + 2*SKH + SVH;

    const int tid  = threadIdx.x;
    const int lane = tid & 31, w = tid >> 5;
    const int g = lane >> 2, l = lane & 3;
    const int lr = lane & 15, lc = lane >> 4;
    const int qt = blockIdx.x, h = blockIdx.y, b = blockIdx.z;

    const size_t hb = (size_t)(b*NHEAD + h) * (NSEQ*DHEAD);
    const __half* Q  = g_q  + hb;
    const __half* K  = g_k  + hb;
    const __half* Vt = g_vt + hb;

    auto load_kv = [&](__half* dK, __half* dV, int kt) {
#pragma unroll
        for (int i = 0; i < 8; i++) {
            int id = tid + i*128;
            int r = id >> 3, c = id & 7;
            cp16(&dK[r*72 + c*8], K + (size_t)(kt*128 + r)*DHEAD + c*8);
        }
#pragma unroll
        for (int i = 0; i < 8; i++) {
            int id = tid + i*128;
            int r = id >> 4, c = id & 15;
            cp16(&dV[r*136 + c*8], Vt + (size_t)r*NSEQ + kt*128 + c*8);
        }
    };

#pragma unroll
    for (int i = 0; i < 4; i++) {
        int id = tid + i*128;
        int r = id >> 3, c = id & 7;
        cp16(&sK1[r*72 + c*8], Q + (size_t)(qt*64 + r)*DHEAD + c*8);
    }
    load_kv(sK0, sV0, 0);
    CP_COMMIT();
    CP_WAIT0(); __syncthreads();

    uint32_t qf[4][4];
#pragma unroll
    for (int kk = 0; kk < 4; kk++) {
        const __half* p = &sK1[(w*16 + lr)*72 + kk*16 + lc*8];
        ldsm_x4(qf[kk][0], qf[kk][1], qf[kk][2], qf[kk][3], p);
    }
    {
        const float qs = 0.125f * 1.4426950408889634f;   // 1/sqrt(DH) * log2(e)
        __half2 s2 = __floats2half2_rn(qs, qs);
#pragma unroll
        for (int kk = 0; kk < 4; kk++)
#pragma unroll
            for (int j = 0; j < 4; j++) {
                __half2 v = *reinterpret_cast<__half2*>(&qf[kk][j]);
                v = __hmul2(v, s2);
                qf[kk][j] = *reinterpret_cast<uint32_t*>(&v);
            }
    }
    __syncthreads();

    load_kv(sK1, sV1, 1);
    CP_COMMIT();

    float oacc[8][4];
#pragma unroll
    for (int d = 0; d < 8; d++)
#pragma unroll
        for (int r = 0; r < 4; r++) oacc[d][r] = 0.f;
    float macc[4] = {0.f, 0.f, 0.f, 0.f};

    const int KT = NSEQ/128;         // 16
    for (int kt = 0; kt < KT; kt += 2) {
        if (kt + 1 < KT) CP_WAIT1(); else CP_WAIT0();
        __syncthreads();
        attn_tile(sK0, sV0, qf, oacc, macc, g, l);
        __syncthreads();
        if (kt + 2 < KT) { load_kv(sK0, sV0, kt + 2); CP_COMMIT(); }
        if (kt + 2 < KT) CP_WAIT1(); else CP_WAIT0();
        __syncthreads();
        attn_tile(sK1, sV1, qf, oacc, macc, g, l);
        __syncthreads();
        if (kt + 3 < KT) { load_kv(sK1, sV1, kt + 3); CP_COMMIT(); }
    }

#pragma unroll
    for (int r = 0; r < 2; r++) {
        float inv = 1.f / macc[r*2];
        int qrow = qt*64 + w*16 + g + r*8;
        __half* dst = g_at + (size_t)(b*NSEQ + qrow)*DMODEL + h*DHEAD;
#pragma unroll
        for (int d = 0; d < 8; d++) {
            *reinterpret_cast<__half2*>(dst + d*8 + 2*l) =
                __floats2half2_rn(oacc[d][r*2]*inv, oacc[d][r*2+1]*inv);
        }
    }
}

// ---------------- launch ----------------
extern "C" void kernel_launch(void* const* d_in, const int* in_sizes, int n_in,
                              void* d_out, int out_size) {
    const float* xq = (const float*)d_in[0];
    const float* xk = (const float*)d_in[1];
    const float* xv = (const float*)d_in[2];
    const float* Wq = (const float*)d_in[3];
    const float* bq = (const float*)d_in[4];
    const float* Wk = (const float*)d_in[5];
    const float* bk = (const float*)d_in[6];
    const float* Wv = (const float*)d_in[7];
    const float* bv = (const float*)d_in[8];
    const float* Wo = (const float*)d_in[9];
    const float* bo = (const float*)d_in[10];
    float* out = (float*)d_out;

    cudaFuncSetAttribute(attn_kernel,
                         cudaFuncAttributeMaxDynamicSharedMemorySize, ATTN_SMEM);
    cudaFuncSetAttribute(gemm_qkv,
                         cudaFuncAttributeMaxDynamicSharedMemorySize, GEMM_SMEM);
    cudaFuncSetAttribute(gemm_o,
                         cudaFuncAttributeMaxDynamicSharedMemorySize, GEMM_SMEM);

    conv_all<<<16384, 256>>>(xq, xk, xv, Wq, Wk, Wv, Wo);          // launch 1

    dim3 qkvgrid(DMODEL/GBN, MTOT/GBM, 3);                          // (8, 32, 3)
    gemm_qkv<<<qkvgrid, 256, GEMM_SMEM>>>(bq, bk, bv);              // launch 2

    attn_kernel<<<dim3(NSEQ/64, NHEAD, BATCH), 128, ATTN_SMEM>>>(); // launch 3

    dim3 ogrid(DMODEL/GBN, MTOT/GBM);                               // (8, 32)
    gemm_o<<<ogrid, 256, GEMM_SMEM>>>(bo, out);                     // launch 4 -> ncu
}